// round 2
// baseline (speedup 1.0000x reference)
#include <cuda_runtime.h>
#include <cstdint>

// AtomicConv: E=640000, N=20000, K=16, T=8.
//
// CRITICAL semantics detail: the reference does a RAW reshape of the pooled
// tensor from (K,E,1) to (E,K) (C-order, not a transpose). Therefore:
//   he[e,k] = f_{k'}(d[e'']) with k' = (e*K+k)//E, e'' = (e*K+k)%E.
// Since E = K * 40000, for every edge e all 16 values share
//   k'  = e / 40000            (one radial-param triple per edge)
//   e'' = 16*(e % 40000) + k   (16 CONSECUTIVE distances -> 4x float4)
// Then: out[dst[e], ti*16 + k] += he[e,k], ti = one_hot index of feat[src[e]]
// (at most one match; no match -> edge contributes nothing).

#define K_RADIAL 16
#define N_TYPES  8
#define E_PER_K  40000
#define PI_F     3.14159265358979323846f

__global__ void __launch_bounds__(256)
atomic_conv_edge_kernel(const float* __restrict__ feat,
                        const float* __restrict__ dist,
                        const float* __restrict__ rparams,   // (K,3): cutoff, mean, scaling
                        const float* __restrict__ ftu,       // (T,)
                        const int*   __restrict__ src,
                        const int*   __restrict__ dst,
                        float*       __restrict__ out,       // (N, T*K), pre-zeroed
                        int n_edges)
{
    __shared__ float s_cut[K_RADIAL];
    __shared__ float s_mean[K_RADIAL];
    __shared__ float s_scl[K_RADIAL];
    __shared__ float s_pic[K_RADIAL];   // pi / cutoff
    __shared__ float s_ftu[N_TYPES];

    const int tid = threadIdx.x;
    if (tid < K_RADIAL) {
        float c = rparams[tid * 3 + 0];
        s_cut[tid]  = c;
        s_mean[tid] = rparams[tid * 3 + 1];
        s_scl[tid]  = rparams[tid * 3 + 2];
        s_pic[tid]  = PI_F / c;
    }
    if (tid < N_TYPES) s_ftu[tid] = ftu[tid];
    __syncthreads();

    const int e = blockIdx.x * blockDim.x + tid;
    if (e >= n_edges) return;

    const int   sn = src[e];
    const int   dn = dst[e];
    const float f  = __ldg(&feat[sn]);

    // one-hot type index (at most one match; -1 = skip edge)
    int ti = -1;
    #pragma unroll
    for (int t = 0; t < N_TYPES; t++)
        if (f == s_ftu[t]) ti = t;
    if (ti < 0) return;

    // radial kernel index + distance base per the raw (K,E)->(E,K) reshape
    const int kp = e / E_PER_K;                // kernel row
    const int eb = (e - kp * E_PER_K) * 16;    // distance base index

    const float cut  = s_cut[kp];
    const float mean = s_mean[kp];
    const float scl  = s_scl[kp];
    const float pic  = s_pic[kp];

    const float4* dp = (const float4*)(dist + eb);
    float* base = out + (size_t)dn * (N_TYPES * K_RADIAL) + ti * K_RADIAL;

    #pragma unroll
    for (int k4 = 0; k4 < 4; k4++) {
        const float4 d4 = __ldg(&dp[k4]);
        float v[4];
        const float dd[4] = {d4.x, d4.y, d4.z, d4.w};
        #pragma unroll
        for (int j = 0; j < 4; j++) {
            const float d   = dd[j];
            const float dm  = d - mean;
            const float rbf = __expf(-scl * dm * dm);
            float cv = 0.0f;
            if (d <= cut)
                cv = 0.5f * (__cosf(pic * d) + 1.0f);
            v[j] = rbf * cv;
        }
        asm volatile("red.global.add.v4.f32 [%0], {%1, %2, %3, %4};"
                     :: "l"(base + k4 * 4),
                        "f"(v[0]), "f"(v[1]), "f"(v[2]), "f"(v[3])
                     : "memory");
    }
}

extern "C" void kernel_launch(void* const* d_in, const int* in_sizes, int n_in,
                              void* d_out, int out_size)
{
    const float* feat    = (const float*)d_in[0];   // (N,1)
    const float* dist    = (const float*)d_in[1];   // (E,1)
    const float* rparams = (const float*)d_in[2];   // (K,3)
    const float* ftu     = (const float*)d_in[3];   // (T,)
    const int*   src     = (const int*)d_in[4];     // (E,)
    const int*   dst     = (const int*)d_in[5];     // (E,)
    float*       out     = (float*)d_out;           // (N, T*K)

    const int n_edges = in_sizes[1];

    cudaMemsetAsync(out, 0, (size_t)out_size * sizeof(float), 0);

    const int threads = 256;
    const int blocks  = (n_edges + threads - 1) / threads;
    atomic_conv_edge_kernel<<<blocks, threads>>>(feat, dist, rparams, ftu,
                                                 src, dst, out, n_edges);
}

// round 6
// speedup vs baseline: 1.1157x; 1.1157x over previous
#include <cuda_runtime.h>
#include <cstdint>

// AtomicConv: E=640000, N=20000, K=16, T=8.
//
// Semantics (raw (K,E,1)->(E,K) reshape in the reference):
//   for edge e: kp = e/40000 (one radial kernel), distances d[16*(e%40000)+k]
//   out[dst[e], ti*16+k] += exp(-s(d-m)^2) * 0.5*(cos(pi*d/c)+1)*[d<=c]
//   ti = one-hot index of feat[src[e]] in features_to_use (miss -> skip edge)
//
// Plan: (0) 1-thread kernel zeroes the worklist counter,
//       (1) compact active edges into a worklist (also zero out),
//       (2) dense scatter kernel, 4 lanes per edge (one float4/k-quad each)
//       -> coalesced dist loads + 64B-chunked red.global.add.v4.f32.

#define K_RADIAL 16
#define N_TYPES  8
#define E_PER_K  40000
#define MAX_E    640000
#define PI_F     3.14159265358979323846f

__device__ int  g_count;
__device__ int2 g_wl[MAX_E];   // {out_base_offset, edge_id}

// ------------------------------------------------------------------- init
__global__ void init_kernel()
{
    g_count = 0;
}

// ---------------------------------------------------------------- compaction
__global__ void __launch_bounds__(256)
compact_zero_kernel(const float* __restrict__ feat,
                    const float* __restrict__ ftu,
                    const int*   __restrict__ src,
                    const int*   __restrict__ dst,
                    float*       __restrict__ out,
                    int n_edges, int n_out4)
{
    __shared__ int s_cnt;
    __shared__ int s_base;
    const int tid = threadIdx.x;
    const int e   = blockIdx.x * blockDim.x + tid;

    if (tid == 0) s_cnt = 0;

    // zero the output (E threads cover out_size/4 float4s exactly)
    if (e < n_out4)
        ((float4*)out)[e] = make_float4(0.f, 0.f, 0.f, 0.f);

    const float f0 = ftu[0], f1 = ftu[1], f2 = ftu[2], f3 = ftu[3];
    const float f4 = ftu[4], f5 = ftu[5], f6 = ftu[6], f7 = ftu[7];

    __syncthreads();

    int ti = -1, dn = 0;
    if (e < n_edges) {
        const int sn = src[e];
        dn = dst[e];
        const float f = __ldg(&feat[sn]);
        if (f == f0) ti = 0;  if (f == f1) ti = 1;
        if (f == f2) ti = 2;  if (f == f3) ti = 3;
        if (f == f4) ti = 4;  if (f == f5) ti = 5;
        if (f == f6) ti = 6;  if (f == f7) ti = 7;
    }

    int local = 0;
    if (ti >= 0) local = atomicAdd(&s_cnt, 1);
    __syncthreads();
    if (tid == 0) s_base = atomicAdd(&g_count, s_cnt);
    __syncthreads();

    if (ti >= 0)
        g_wl[s_base + local] = make_int2(dn * (N_TYPES * K_RADIAL) + ti * K_RADIAL, e);
}

// ------------------------------------------------------------------ scatter
__global__ void __launch_bounds__(256)
scatter_kernel(const float* __restrict__ dist,
               const float* __restrict__ rparams,   // (K,3)
               float*       __restrict__ out)
{
    __shared__ float s_cut[K_RADIAL];
    __shared__ float s_mean[K_RADIAL];
    __shared__ float s_scl[K_RADIAL];
    __shared__ float s_pic[K_RADIAL];

    const int tid = threadIdx.x;
    if (tid < K_RADIAL) {
        float c = rparams[tid * 3 + 0];
        s_cut[tid]  = c;
        s_mean[tid] = rparams[tid * 3 + 1];
        s_scl[tid]  = rparams[tid * 3 + 2];
        s_pic[tid]  = PI_F / c;
    }
    __syncthreads();

    const int count  = g_count;
    const int stride = gridDim.x * blockDim.x;

    for (int i = blockIdx.x * blockDim.x + tid; ; i += stride) {
        const int g = i >> 2;           // worklist entry (edge)
        if (g >= count) break;
        const int k4 = i & 3;           // which k-quad this lane owns

        const int2 w  = g_wl[g];
        const unsigned e  = (unsigned)w.y;
        const unsigned kp = e / E_PER_K;
        const int      eb = (int)(e - kp * E_PER_K) * 16;

        const float cut  = s_cut[kp];
        const float mean = s_mean[kp];
        const float scl  = s_scl[kp];
        const float pic  = s_pic[kp];

        const float4 d4 = __ldg((const float4*)(dist + eb) + k4);
        const float dd[4] = {d4.x, d4.y, d4.z, d4.w};

        float v[4];
        #pragma unroll
        for (int j = 0; j < 4; j++) {
            const float d   = dd[j];
            const float dm  = d - mean;
            const float rbf = __expf(-scl * dm * dm);
            float cv = 0.0f;
            if (d <= cut)
                cv = 0.5f * (__cosf(pic * d) + 1.0f);
            v[j] = rbf * cv;
        }

        float* addr = out + w.x + k4 * 4;
        asm volatile("red.global.add.v4.f32 [%0], {%1, %2, %3, %4};"
                     :: "l"(addr), "f"(v[0]), "f"(v[1]), "f"(v[2]), "f"(v[3])
                     : "memory");
    }
}

// ------------------------------------------------------------------- launch
extern "C" void kernel_launch(void* const* d_in, const int* in_sizes, int n_in,
                              void* d_out, int out_size)
{
    const float* feat    = (const float*)d_in[0];   // (N,1)
    const float* dist    = (const float*)d_in[1];   // (E,1)
    const float* rparams = (const float*)d_in[2];   // (K,3)
    const float* ftu     = (const float*)d_in[3];   // (T,)
    const int*   src     = (const int*)d_in[4];     // (E,)
    const int*   dst     = (const int*)d_in[5];     // (E,)
    float*       out     = (float*)d_out;           // (N, T*K)

    const int n_edges = in_sizes[1];
    const int n_out4  = out_size / 4;

    init_kernel<<<1, 1>>>();

    const int threads = 256;
    const int cblocks = (n_edges + threads - 1) / threads;
    compact_zero_kernel<<<cblocks, threads>>>(feat, ftu, src, dst, out,
                                              n_edges, n_out4);

    scatter_kernel<<<1184, threads>>>(dist, rparams, out);
}